// round 8
// baseline (speedup 1.0000x reference)
#include <cuda_runtime.h>

#define HW   3136
#define WD   56
#define NB   32
#define CIN  240
#define MID  120
#define COUT 480

// Scratch (allocation-free rule: __device__ globals)
__device__ float g_y1[(size_t)NB * MID * HW];   // conv1 output (post BN+ReLU)
__device__ float g_y2[(size_t)NB * MID * HW];   // depthwise output, SHUFFLED channel order

typedef unsigned long long u64;

__device__ __forceinline__ u64 pack2(float a, float b) {
    u64 r; asm("mov.b64 %0, {%1, %2};" : "=l"(r) : "f"(a), "f"(b)); return r;
}
__device__ __forceinline__ u64 fma2(u64 a, u64 b, u64 c) {
    u64 d; asm("fma.rn.f32x2 %0, %1, %2, %3;" : "=l"(d) : "l"(a), "l"(b), "l"(c)); return d;
}
__device__ __forceinline__ float2 unpack2(u64 v) {
    float2 r; asm("mov.b64 {%0, %1}, %2;" : "=f"(r.x), "=f"(r.y) : "l"(v)); return r;
}

// ---------------------------------------------------------------------------
// K1: grouped 1x1 conv (per group: 40oc x 80ic) + BN + ReLU -> g_y1
// grid (49, 3, 32), block 160 = ty(10 x 4oc) * tx(16 x 4hw)
// ---------------------------------------------------------------------------
__global__ __launch_bounds__(160) void conv1_kernel(
    const float* __restrict__ x, const float* __restrict__ w1,
    const float* __restrict__ scale1, const float* __restrict__ shift1)
{
    __shared__ __align__(16) float sX[16][64];
    __shared__ __align__(16) float sW[16][40];
    const int tid = threadIdx.x;
    const int tx = tid & 15, ty = tid >> 4;      // ty: 0..9
    const int n = blockIdx.z, g = blockIdx.y;
    const int hw0 = blockIdx.x * 64;
    const float* xg = x + ((size_t)n * CIN + g * 80) * HW;
    const float* wg = w1 + g * 40 * 80;

    u64 acc[2][4];
    #pragma unroll
    for (int i = 0; i < 2; i++)
        #pragma unroll
        for (int j = 0; j < 4; j++) acc[i][j] = 0ull;

    for (int kk = 0; kk < 80; kk += 16) {
        for (int idx = tid; idx < 16 * 64; idx += 160) {
            int k = idx >> 6, j = idx & 63;
            sX[k][j] = xg[(size_t)(kk + k) * HW + hw0 + j];
        }
        for (int idx = tid; idx < 16 * 40; idx += 160) {
            int oc = idx >> 4, k = idx & 15;
            sW[k][oc] = wg[oc * 80 + kk + k];
        }
        __syncthreads();
        #pragma unroll
        for (int k = 0; k < 16; k++) {
            ulonglong2 wv = *(const ulonglong2*)&sW[k][ty * 4];
            float4 xv = *(const float4*)&sX[k][tx * 4];
            u64 x0 = pack2(xv.x, xv.x), x1 = pack2(xv.y, xv.y);
            u64 x2 = pack2(xv.z, xv.z), x3 = pack2(xv.w, xv.w);
            acc[0][0] = fma2(wv.x, x0, acc[0][0]); acc[0][1] = fma2(wv.x, x1, acc[0][1]);
            acc[0][2] = fma2(wv.x, x2, acc[0][2]); acc[0][3] = fma2(wv.x, x3, acc[0][3]);
            acc[1][0] = fma2(wv.y, x0, acc[1][0]); acc[1][1] = fma2(wv.y, x1, acc[1][1]);
            acc[1][2] = fma2(wv.y, x2, acc[1][2]); acc[1][3] = fma2(wv.y, x3, acc[1][3]);
        }
        __syncthreads();
    }

    float* yb = g_y1 + (size_t)n * MID * HW;
    #pragma unroll
    for (int r = 0; r < 4; r++) {
        int oc = g * 40 + ty * 4 + r;
        float sc = scale1[oc], sh = shift1[oc];
        int i = r >> 1, lane = r & 1;
        float2 v0 = unpack2(acc[i][0]), v1 = unpack2(acc[i][1]);
        float2 v2 = unpack2(acc[i][2]), v3 = unpack2(acc[i][3]);
        float a0 = lane ? v0.y : v0.x, a1 = lane ? v1.y : v1.x;
        float a2 = lane ? v2.y : v2.x, a3 = lane ? v3.y : v3.x;
        float4 o;
        o.x = fmaxf(fmaf(a0, sc, sh), 0.f);
        o.y = fmaxf(fmaf(a1, sc, sh), 0.f);
        o.z = fmaxf(fmaf(a2, sc, sh), 0.f);
        o.w = fmaxf(fmaf(a3, sc, sh), 0.f);
        *(float4*)&yb[(size_t)oc * HW + hw0 + tx * 4] = o;
    }
}

// ---------------------------------------------------------------------------
// K2: depthwise 3x3 (pad 1) + BN2, write in SHUFFLED channel order.
// shuffled[d] = in[(d%3)*40 + d/3]  =>  source c writes to dst = (c%40)*3 + c/40
// grid ((HW+255)/256, 120, 32), block 256
// ---------------------------------------------------------------------------
__global__ __launch_bounds__(256) void dw_kernel(
    const float* __restrict__ w2, const float* __restrict__ scale2,
    const float* __restrict__ shift2)
{
    const int n = blockIdx.z, c = blockIdx.y;
    const int p = blockIdx.x * 256 + threadIdx.x;
    if (p >= HW) return;
    const int h = p / WD, w = p % WD;
    const float* src = g_y1 + ((size_t)n * MID + c) * HW;
    const float* wr = w2 + c * 9;
    float s = 0.f;
    #pragma unroll
    for (int kh = 0; kh < 3; kh++) {
        int hh = h + kh - 1;
        if (hh < 0 || hh >= WD) continue;
        const float* row = src + hh * WD;
        #pragma unroll
        for (int kw = 0; kw < 3; kw++) {
            int ww = w + kw - 1;
            if (ww >= 0 && ww < WD) s = fmaf(row[ww], wr[kh * 3 + kw], s);
        }
    }
    float v = fmaf(s, scale2[c], shift2[c]);
    const int dst = (c % 40) * 3 + c / 40;
    g_y2[((size_t)n * MID + dst) * HW + p] = v;
}

// ---------------------------------------------------------------------------
// K3: grouped 1x1 conv3 (per oc-group 160: 40 shuffled ic) + BN3 + ReLU,
//     plus full 1x1 shortcut (240 ic) + BN_sc, fused add -> out.
// grid (49, 6, 32), block 160 = ty(10 x 8oc) * tx(16 x 4hw); tile 80oc x 64hw
// ---------------------------------------------------------------------------
__global__ __launch_bounds__(160) void conv3_kernel(
    const float* __restrict__ x,
    const float* __restrict__ w3, const float* __restrict__ scale3,
    const float* __restrict__ shift3,
    const float* __restrict__ wsc, const float* __restrict__ scale_sc,
    const float* __restrict__ shift_sc,
    float* __restrict__ out)
{
    __shared__ __align__(16) float sX[16][64];
    __shared__ __align__(16) float sW[16][80];
    const int tid = threadIdx.x;
    const int tx = tid & 15, ty = tid >> 4;      // ty: 0..9
    const int n = blockIdx.z;
    const int oc_base = blockIdx.y * 80;         // 80-tile stays inside a 160-group
    const int hw0 = blockIdx.x * 64;
    const int gsel = oc_base / 160;

    u64 acc[4][4];
    #pragma unroll
    for (int i = 0; i < 4; i++)
        #pragma unroll
        for (int j = 0; j < 4; j++) acc[i][j] = 0ull;

    // ---- phase 1: conv3 over 40 shuffled channels (padded to 48)
    const float* y2g = g_y2 + ((size_t)n * MID + gsel * 40) * HW;
    for (int kk = 0; kk < 48; kk += 16) {
        for (int idx = tid; idx < 16 * 64; idx += 160) {
            int k = idx >> 6, j = idx & 63, kg = kk + k;
            sX[k][j] = (kg < 40) ? y2g[(size_t)kg * HW + hw0 + j] : 0.f;
        }
        for (int idx = tid; idx < 16 * 80; idx += 160) {
            int oc = idx >> 4, k = idx & 15, kg = kk + k;
            sW[k][oc] = (kg < 40) ? w3[(oc_base + oc) * 40 + kg] : 0.f;
        }
        __syncthreads();
        #pragma unroll
        for (int k = 0; k < 16; k++) {
            ulonglong2 wa = *(const ulonglong2*)&sW[k][ty * 8];
            ulonglong2 wb = *(const ulonglong2*)&sW[k][ty * 8 + 4];
            float4 xv = *(const float4*)&sX[k][tx * 4];
            u64 x0 = pack2(xv.x, xv.x), x1 = pack2(xv.y, xv.y);
            u64 x2 = pack2(xv.z, xv.z), x3 = pack2(xv.w, xv.w);
            acc[0][0] = fma2(wa.x, x0, acc[0][0]); acc[0][1] = fma2(wa.x, x1, acc[0][1]);
            acc[0][2] = fma2(wa.x, x2, acc[0][2]); acc[0][3] = fma2(wa.x, x3, acc[0][3]);
            acc[1][0] = fma2(wa.y, x0, acc[1][0]); acc[1][1] = fma2(wa.y, x1, acc[1][1]);
            acc[1][2] = fma2(wa.y, x2, acc[1][2]); acc[1][3] = fma2(wa.y, x3, acc[1][3]);
            acc[2][0] = fma2(wb.x, x0, acc[2][0]); acc[2][1] = fma2(wb.x, x1, acc[2][1]);
            acc[2][2] = fma2(wb.x, x2, acc[2][2]); acc[2][3] = fma2(wb.x, x3, acc[2][3]);
            acc[3][0] = fma2(wb.y, x0, acc[3][0]); acc[3][1] = fma2(wb.y, x1, acc[3][1]);
            acc[3][2] = fma2(wb.y, x2, acc[3][2]); acc[3][3] = fma2(wb.y, x3, acc[3][3]);
        }
        __syncthreads();
    }

    // BN3 + ReLU held in registers
    float2 yr[4][4];
    #pragma unroll
    for (int i = 0; i < 4; i++) {
        int oc0 = oc_base + ty * 8 + 2 * i;
        float s0 = scale3[oc0], b0 = shift3[oc0];
        float s1 = scale3[oc0 + 1], b1 = shift3[oc0 + 1];
        #pragma unroll
        for (int j = 0; j < 4; j++) {
            float2 v = unpack2(acc[i][j]);
            yr[i][j].x = fmaxf(fmaf(v.x, s0, b0), 0.f);
            yr[i][j].y = fmaxf(fmaf(v.y, s1, b1), 0.f);
            acc[i][j] = 0ull;   // reuse for shortcut
        }
    }

    // ---- phase 2: shortcut GEMM over all 240 input channels
    const float* xn = x + (size_t)n * CIN * HW;
    for (int kk = 0; kk < 240; kk += 16) {
        for (int idx = tid; idx < 16 * 64; idx += 160) {
            int k = idx >> 6, j = idx & 63;
            sX[k][j] = xn[(size_t)(kk + k) * HW + hw0 + j];
        }
        for (int idx = tid; idx < 16 * 80; idx += 160) {
            int oc = idx >> 4, k = idx & 15;
            sW[k][oc] = wsc[(oc_base + oc) * 240 + kk + k];
        }
        __syncthreads();
        #pragma unroll
        for (int k = 0; k < 16; k++) {
            ulonglong2 wa = *(const ulonglong2*)&sW[k][ty * 8];
            ulonglong2 wb = *(const ulonglong2*)&sW[k][ty * 8 + 4];
            float4 xv = *(const float4*)&sX[k][tx * 4];
            u64 x0 = pack2(xv.x, xv.x), x1 = pack2(xv.y, xv.y);
            u64 x2 = pack2(xv.z, xv.z), x3 = pack2(xv.w, xv.w);
            acc[0][0] = fma2(wa.x, x0, acc[0][0]); acc[0][1] = fma2(wa.x, x1, acc[0][1]);
            acc[0][2] = fma2(wa.x, x2, acc[0][2]); acc[0][3] = fma2(wa.x, x3, acc[0][3]);
            acc[1][0] = fma2(wa.y, x0, acc[1][0]); acc[1][1] = fma2(wa.y, x1, acc[1][1]);
            acc[1][2] = fma2(wa.y, x2, acc[1][2]); acc[1][3] = fma2(wa.y, x3, acc[1][3]);
            acc[2][0] = fma2(wb.x, x0, acc[2][0]); acc[2][1] = fma2(wb.x, x1, acc[2][1]);
            acc[2][2] = fma2(wb.x, x2, acc[2][2]); acc[2][3] = fma2(wb.x, x3, acc[2][3]);
            acc[3][0] = fma2(wb.y, x0, acc[3][0]); acc[3][1] = fma2(wb.y, x1, acc[3][1]);
            acc[3][2] = fma2(wb.y, x2, acc[3][2]); acc[3][3] = fma2(wb.y, x3, acc[3][3]);
        }
        __syncthreads();
    }

    // final: relu(BN3(conv3)) + BN_sc(shortcut), float4 stores
    float* ob = out + (size_t)n * COUT * HW;
    #pragma unroll
    for (int r = 0; r < 8; r++) {
        int oc = oc_base + ty * 8 + r;
        int i = r >> 1, lane = r & 1;
        float ss = scale_sc[oc], sb = shift_sc[oc];
        float2 v0 = unpack2(acc[i][0]), v1 = unpack2(acc[i][1]);
        float2 v2 = unpack2(acc[i][2]), v3 = unpack2(acc[i][3]);
        float z0 = lane ? v0.y : v0.x, z1 = lane ? v1.y : v1.x;
        float z2 = lane ? v2.y : v2.x, z3 = lane ? v3.y : v3.x;
        float y0 = lane ? yr[i][0].y : yr[i][0].x;
        float y1 = lane ? yr[i][1].y : yr[i][1].x;
        float y2 = lane ? yr[i][2].y : yr[i][2].x;
        float y3 = lane ? yr[i][3].y : yr[i][3].x;
        float4 o;
        o.x = fmaf(z0, ss, sb) + y0;
        o.y = fmaf(z1, ss, sb) + y1;
        o.z = fmaf(z2, ss, sb) + y2;
        o.w = fmaf(z3, ss, sb) + y3;
        *(float4*)&ob[(size_t)oc * HW + hw0 + tx * 4] = o;
    }
}

// ---------------------------------------------------------------------------
extern "C" void kernel_launch(void* const* d_in, const int* in_sizes, int n_in,
                              void* d_out, int out_size)
{
    const float* x        = (const float*)d_in[0];
    const float* w1       = (const float*)d_in[1];
    const float* scale1   = (const float*)d_in[2];
    const float* shift1   = (const float*)d_in[3];
    const float* w2       = (const float*)d_in[4];
    const float* scale2   = (const float*)d_in[5];
    const float* shift2   = (const float*)d_in[6];
    const float* w3       = (const float*)d_in[7];
    const float* scale3   = (const float*)d_in[8];
    const float* shift3   = (const float*)d_in[9];
    const float* wsc      = (const float*)d_in[10];
    const float* scale_sc = (const float*)d_in[11];
    const float* shift_sc = (const float*)d_in[12];
    // d_in[13] = groups (always 3), baked in at compile time
    float* out = (float*)d_out;

    conv1_kernel<<<dim3(49, 3, NB), 160>>>(x, w1, scale1, shift1);
    dw_kernel<<<dim3((HW + 255) / 256, MID, NB), 256>>>(w2, scale2, shift2);
    conv3_kernel<<<dim3(49, 6, NB), 160>>>(x, w3, scale3, shift3,
                                           wsc, scale_sc, shift_sc, out);
}